// round 14
// baseline (speedup 1.0000x reference)
#include <cuda_runtime.h>

typedef unsigned long long ull;

// Problem constants (fixed by the dataset)
#define NBATCH 8192
#define NEL    16      // NUP + NDOWN
#define NSP    8
#define NMO    32
#define NCONF  64

#define PIV_THRESH 2.5e-4f   // N(0,1) inputs; below this, redo with pivoting

#define BPB     2                 // batches per block
#define THREADS (BPB * NCONF)     // 128

__device__ __forceinline__ float frcp(float x) {
    float r;
    asm("rcp.approx.f32 %0, %1;" : "=f"(r) : "f"(x));
    return r;
}

// f32x2 helpers: 64-bit carrier holds (lo=row 2p, hi=row 2p+1).
__device__ __forceinline__ ull pack2(float x) {
    ull r;
    asm("mov.b64 %0, {%1, %1};" : "=l"(r) : "r"(__float_as_uint(x)));
    return r;
}
__device__ __forceinline__ ull pack_pair(float lo, float hi) {
    ull r;
    asm("mov.b64 %0, {%1, %2};" : "=l"(r) : "f"(lo), "f"(hi));
    return r;
}
__device__ __forceinline__ float lo2(ull v) {
    return __uint_as_float((unsigned)v);
}
__device__ __forceinline__ float hi2(ull v) {
    return __uint_as_float((unsigned)(v >> 32));
}
__device__ __forceinline__ ull ffma2(ull a, ull b, ull c) {   // a*b + c, packed
    ull d;
    asm("fma.rn.f32x2 %0, %1, %2, %3;" : "=l"(d) : "l"(a), "l"(b), "l"(c));
    return d;
}

// ---------------------------------------------------------------------------
// ONE THREAD = ONE (batch, config) pair; block = 2 batches x 64 configs.
//
// F-matrix column-op Gauss-Jordan: apply column ops to A only, accumulating
// them in F (starting from I). Then A*F = D (diagonal of pivots), so
// A^-1 = F*D^-1 and
//     tr(A^-1 B) = sum_j (1/d_j) * (F col j) . (B row j)
// with the ORIGINAL B -- B is never transformed (224 FFMA2 saved/spin).
//
// Exact sparsity: at step k, F[:,k] has nonzeros only in rows 0..k
// (induction from F=I), so the F-update touches packed pairs p <= k>>1
// (140 FFMA2). A-update keeps the round-13 dead-pair skip p >= k>>1
// (133 FFMA2). Contraction: 32 FFMA2. Total 305 vs 357 FFMA2 per spin.
//
// SMEM layout [row][NMO+1]: warp-wide gathers hit bank (row+col) mod 32 ->
// conflict-free (duplicates broadcast); holds for the contraction loads too
// (fixed row, distinct cfg columns).
//
// Cleanup (block scope, rare): groups with |pivot| < PIV_THRESH are parked in
// a shared list and re-solved by the block's warps with the proven
// 4-lane/2-row ROW-op Gauss-Jordan + implicit partial pivoting.
// ---------------------------------------------------------------------------
__global__ __launch_bounds__(THREADS, 3)
void kinetic_kernel(const float* __restrict__ MO,
                    const float* __restrict__ d2MO,
                    const int*   __restrict__ cfg_up,
                    const int*   __restrict__ cfg_dn,
                    float*       __restrict__ out)
{
    __shared__ float sMO[BPB][NEL][NMO + 1];   // +1 pad: (row+col) bank spread
    __shared__ float sD2[BPB][NEL][NMO + 1];
    __shared__ int   sBad[THREADS];
    __shared__ int   sNbad;

    const int tid = threadIdx.x;
    const int b0  = blockIdx.x * BPB;

    if (tid == 0) sNbad = 0;

    // Stage: coalesced global reads; smem writes bank-conflict-free.
    #pragma unroll
    for (int i = 0; i < (BPB * NEL * NMO) / THREADS; i++) {
        const int e   = tid + i * THREADS;
        const int bl  = e >> 9;          // /512
        const int rem = e & 511;
        const int row = rem >> 5;        // electron 0..15
        const int col = rem & 31;        // MO 0..31
        sMO[bl][row][col] = MO[(b0 + bl) * NEL * NMO + rem];
        sD2[bl][row][col] = d2MO[(b0 + bl) * NEL * NMO + rem];
    }
    __syncthreads();

    const int bl = tid >> 6;   // batch within block
    const int c  = tid & 63;   // config

    float trsum   = 0.0f;
    float detprod = 1.0f;
    float minpiv  = 1e30f;

    #pragma unroll 1
    for (int spin = 0; spin < 2; spin++) {
        const int4* cp = (const int4*)((spin ? cfg_dn : cfg_up) + c * NSP);
        const int4  cA = cp[0];
        const int4  cB = cp[1];
        const int   cfg[8] = { cA.x, cA.y, cA.z, cA.w, cB.x, cB.y, cB.z, cB.w };
        const int   roff = spin ? NSP : 0;

        // A: 8 columns x 4 packed row-pairs (conflict-free scalar gathers).
        // F: starts as identity, packed the same way.
        ull A[8][4], F[8][4];
        #pragma unroll
        for (int j = 0; j < 8; j++) {
            const float* pa = &sMO[bl][roff][cfg[j]];
            #pragma unroll
            for (int p = 0; p < 4; p++) {
                A[j][p] = pack_pair(pa[(2 * p) * (NMO + 1)],
                                    pa[(2 * p + 1) * (NMO + 1)]);
                F[j][p] = (p == (j >> 1))
                        ? ((j & 1) ? pack_pair(0.0f, 1.0f) : pack_pair(1.0f, 0.0f))
                        : 0ull;
            }
        }

        float det = 1.0f;

        #pragma unroll
        for (int k = 0; k < 8; k++) {
            const float piv = (k & 1) ? hi2(A[k][k >> 1]) : lo2(A[k][k >> 1]);
            const float nr  = -frcp(piv);
            minpiv = fminf(minpiv, fabsf(piv));
            det   *= piv;

            #pragma unroll
            for (int j = 0; j < 8; j++) {
                if (j == k) continue;
                const float akj = (k & 1) ? hi2(A[j][k >> 1]) : lo2(A[j][k >> 1]);
                const ull   nm  = pack2(akj * nr);   // (-m_j, -m_j)
                if (k < 7) {                          // A irrelevant after step 7
                    #pragma unroll
                    for (int p = 0; p < 4; p++)
                        if (p >= (k >> 1))            // rows < k of A col k ~ 0
                            A[j][p] = ffma2(nm, A[k][p], A[j][p]);
                }
                #pragma unroll
                for (int p = 0; p < 4; p++)
                    if (p <= (k >> 1))                // rows > k of F col k == 0
                        F[j][p] = ffma2(nm, F[k][p], F[j][p]);
            }
        }

        // Contraction: tr = sum_j (F col j).(B row j) / d_j, B original.
        float tr = 0.0f;
        #pragma unroll
        for (int j = 0; j < 8; j++) {
            const float dj = (j & 1) ? hi2(A[j][j >> 1]) : lo2(A[j][j >> 1]);
            const float* pb = &sD2[bl][roff + j][0];
            ull acc = pack_pair(0.0f, 0.0f);
            #pragma unroll
            for (int p = 0; p < 4; p++) {
                const ull br = pack_pair(pb[cfg[2 * p]], pb[cfg[2 * p + 1]]);
                acc = ffma2(F[j][p], br, acc);
            }
            tr = fmaf(lo2(acc) + hi2(acc), frcp(dj), tr);
        }

        trsum   += tr;
        detprod *= det;
    }

    if (minpiv >= PIV_THRESH) {
        out[(b0 + bl) * NCONF + c] = -0.5f * trsum * detprod;
    } else {
        const int s = atomicAdd(&sNbad, 1);   // shared-mem atomic, rare
        sBad[s] = tid;                        // tid encodes (bl, c)
    }
    __syncthreads();

    // ---------------- block-scope cleanup (rare) ----------------
    const int nbad = sNbad;
    if (nbad == 0) return;

    const int ll   = tid & 3;        // lane within 4-lane group
    const int lane = tid & 31;
    const int base = lane & 28;
    const int row0 = 2 * ll;
    const int row1 = 2 * ll + 1;

    for (int p0 = 0; p0 * 32 < nbad; p0++) {
        const int  e      = p0 * 32 + (tid >> 2);
        const bool active = (e < nbad);
        const int  gt  = sBad[active ? e : (nbad - 1)];   // clamp: full-mask shfl
        const int  gbl = gt >> 6;
        const int  gc  = gt & 63;

        float trs = 0.0f, detp = 1.0f;

        #pragma unroll 1
        for (int spin = 0; spin < 2; spin++) {
            const int4* cp = (const int4*)((spin ? cfg_dn : cfg_up) + gc * NSP);
            const int4  cAi = cp[0];
            const int4  cBi = cp[1];
            const int   cfg[8] = { cAi.x, cAi.y, cAi.z, cAi.w,
                                   cBi.x, cBi.y, cBi.z, cBi.w };
            const int   roff = spin ? NSP : 0;

            float c0[8], c1[8], e0[8], e1[8];
            #pragma unroll
            for (int j = 0; j < 8; j++) {
                const int col = cfg[j];
                c0[j] = sMO[gbl][roff + row0][col];
                c1[j] = sMO[gbl][roff + row1][col];
                e0[j] = sD2[gbl][roff + row0][col];
                e1[j] = sD2[gbl][roff + row1][col];
            }

            unsigned done0 = 0u, done1 = 0u;
            int   k0 = 0, k1 = 0;
            float p0v = 1.0f, p1v = 1.0f;
            int   dmask = 0, invtot = 0;

            #pragma unroll
            for (int k = 0; k < 8; k++) {
                unsigned key0 = done0 ? 0u
                    : ((__float_as_uint(fabsf(c0[k])) & 0xFFFFFFF8u) | (unsigned)row0);
                unsigned key1 = done1 ? 0u
                    : ((__float_as_uint(fabsf(c1[k])) & 0xFFFFFFF8u) | (unsigned)row1);
                unsigned key = max(key0, key1);
                key = max(key, __shfl_xor_sync(0xffffffffu, key, 1));
                key = max(key, __shfl_xor_sync(0xffffffffu, key, 2));

                const int  pr   = (int)(key & 7u);
                const int  pa   = base + (pr >> 1);
                const bool ps   = pr & 1;
                const bool isP0 = (row0 == pr);
                const bool isP1 = (row1 == pr);

                float pj[8];
                #pragma unroll
                for (int j = 0; j < 8; j++) {
                    if (j >= k) {
                        const float s = ps ? c1[j] : c0[j];
                        pj[j] = __shfl_sync(0xffffffffu, s, pa);
                    }
                }
                const float r  = frcp(pj[k]);
                const float m0 = isP0 ? 0.0f : c0[k] * r;
                const float m1 = isP1 ? 0.0f : c1[k] * r;

                if (isP0) { p0v = c0[k]; k0 = k; done0 = 1u; }
                if (isP1) { p1v = c1[k]; k1 = k; done1 = 1u; }

                #pragma unroll
                for (int j = 0; j < 8; j++) {
                    if (j > k) {
                        c0[j] = fmaf(-m0, pj[j], c0[j]);
                        c1[j] = fmaf(-m1, pj[j], c1[j]);
                    }
                }
                #pragma unroll
                for (int j = 0; j < 8; j++) {
                    const float s = ps ? e1[j] : e0[j];
                    const float q = __shfl_sync(0xffffffffu, s, pa);
                    e0[j] = fmaf(-m0, q, e0[j]);
                    e1[j] = fmaf(-m1, q, e1[j]);
                }

                invtot += __popc((unsigned)dmask >> (pr + 1));
                dmask  |= 1 << pr;
            }

            float bv0 = e0[0];
            #pragma unroll
            for (int j = 1; j < 8; j++) bv0 = (k0 == j) ? e0[j] : bv0;
            float bv1 = e1[0];
            #pragma unroll
            for (int j = 1; j < 8; j++) bv1 = (k1 == j) ? e1[j] : bv1;

            const float dd = p0v * p1v;
            float tr  = (bv0 * p1v + bv1 * p0v) * frcp(dd);
            float det = (ll == 0 && (invtot & 1)) ? -dd : dd;

            #pragma unroll
            for (int off = 1; off < 4; off <<= 1) {
                tr  += __shfl_xor_sync(0xffffffffu, tr,  off);
                det *= __shfl_xor_sync(0xffffffffu, det, off);
            }

            trs  += tr;
            detp *= det;
        }

        if (active && ll == 0)
            out[(b0 + gbl) * NCONF + gc] = -0.5f * trs * detp;
    }
}

extern "C" void kernel_launch(void* const* d_in, const int* in_sizes, int n_in,
                              void* d_out, int out_size)
{
    const float* MO     = (const float*)d_in[0];
    const float* d2MO   = (const float*)d_in[1];
    const int*   cfg_up = (const int*)d_in[2];
    const int*   cfg_dn = (const int*)d_in[3];
    float*       out    = (float*)d_out;

    kinetic_kernel<<<NBATCH / BPB, THREADS>>>(MO, d2MO, cfg_up, cfg_dn, out);
}

// round 15
// speedup vs baseline: 1.0478x; 1.0478x over previous
#include <cuda_runtime.h>

typedef unsigned long long ull;

// Problem constants (fixed by the dataset)
#define NBATCH 8192
#define NEL    16      // NUP + NDOWN
#define NSP    8
#define NMO    32
#define NCONF  64

#define PIV_THRESH 2.5e-4f   // N(0,1) inputs; below this, redo with pivoting

#define BPB     2                 // batches per block
#define THREADS (BPB * NCONF)     // 128

__device__ __forceinline__ float frcp(float x) {
    float r;
    asm("rcp.approx.f32 %0, %1;" : "=f"(r) : "f"(x));
    return r;
}

// f32x2 helpers: 64-bit carrier holds (lo=row 2p, hi=row 2p+1).
__device__ __forceinline__ ull pack2(float x) {
    ull r;
    asm("mov.b64 %0, {%1, %1};" : "=l"(r) : "r"(__float_as_uint(x)));
    return r;
}
__device__ __forceinline__ ull pack_pair(float lo, float hi) {
    ull r;
    asm("mov.b64 %0, {%1, %2};" : "=l"(r) : "f"(lo), "f"(hi));
    return r;
}
__device__ __forceinline__ float lo2(ull v) {
    return __uint_as_float((unsigned)v);
}
__device__ __forceinline__ float hi2(ull v) {
    return __uint_as_float((unsigned)(v >> 32));
}
__device__ __forceinline__ ull ffma2(ull a, ull b, ull c) {   // a*b + c, packed
    ull d;
    asm("fma.rn.f32x2 %0, %1, %2, %3;" : "=l"(d) : "l"(a), "l"(b), "l"(c));
    return d;
}

// ---------------------------------------------------------------------------
// ONE THREAD = ONE (batch, config) pair; block = 2 batches x 64 configs.
// Hot path: column-op Gauss-Jordan without pivoting (column ops preserve
// tr(A^-1 B); det = product of pivots), rows packed as f32x2.
//
// Sparsity exploited (all compile-time after unroll):
//  * A-update, step k: source column a[k] has ~0 in rows < k -> only packed
//    pairs p >= k>>1 updated (round-13 dead-pair skip).
//  * B-update, step k: destination columns j < k are RETIRED -- never a
//    source again, only their diagonal B[j][j] (pair j>>1) is read by the
//    epilogue -> ONE ffma2 instead of four. B cost 224 -> 140 FFMA2/spin.
//
// SMEM layout [row][NMO+1]: warp-wide column gathers hit bank
// (row + col) mod 32 -> conflict-free (duplicates broadcast).
//
// Cleanup (block scope, rare): groups with |pivot| < PIV_THRESH are parked in
// a shared list and re-solved by the block's warps with the proven
// 4-lane/2-row ROW-op Gauss-Jordan + implicit partial pivoting.
// ---------------------------------------------------------------------------
__global__ __launch_bounds__(THREADS, 3)
void kinetic_kernel(const float* __restrict__ MO,
                    const float* __restrict__ d2MO,
                    const int*   __restrict__ cfg_up,
                    const int*   __restrict__ cfg_dn,
                    float*       __restrict__ out)
{
    __shared__ float sMO[BPB][NEL][NMO + 1];   // +1 pad: (row+col) bank spread
    __shared__ float sD2[BPB][NEL][NMO + 1];
    __shared__ int   sBad[THREADS];
    __shared__ int   sNbad;

    const int tid = threadIdx.x;
    const int b0  = blockIdx.x * BPB;

    if (tid == 0) sNbad = 0;

    // Stage: coalesced global reads; smem writes bank-conflict-free.
    #pragma unroll
    for (int i = 0; i < (BPB * NEL * NMO) / THREADS; i++) {
        const int e   = tid + i * THREADS;
        const int bl  = e >> 9;          // /512
        const int rem = e & 511;
        const int row = rem >> 5;        // electron 0..15
        const int col = rem & 31;        // MO 0..31
        sMO[bl][row][col] = MO[(b0 + bl) * NEL * NMO + rem];
        sD2[bl][row][col] = d2MO[(b0 + bl) * NEL * NMO + rem];
    }
    __syncthreads();

    const int bl = tid >> 6;   // batch within block
    const int c  = tid & 63;   // config

    float trsum   = 0.0f;
    float detprod = 1.0f;
    float minpiv  = 1e30f;

    #pragma unroll 1
    for (int spin = 0; spin < 2; spin++) {
        const int4* cp = (const int4*)((spin ? cfg_dn : cfg_up) + c * NSP);
        const int4  cA = cp[0];
        const int4  cB = cp[1];
        const int   cfg[8] = { cA.x, cA.y, cA.z, cA.w, cB.x, cB.y, cB.z, cB.w };
        const int   roff = spin ? NSP : 0;

        // A, B: 8 columns x 4 packed row-pairs. Conflict-free scalar gathers
        // (stride 33 within a column), packed to f32x2 in registers.
        ull A[8][4], Bm[8][4];
        #pragma unroll
        for (int j = 0; j < 8; j++) {
            const float* pa = &sMO[bl][roff][cfg[j]];
            const float* pb = &sD2[bl][roff][cfg[j]];
            #pragma unroll
            for (int p = 0; p < 4; p++) {
                A[j][p]  = pack_pair(pa[(2 * p) * (NMO + 1)],
                                     pa[(2 * p + 1) * (NMO + 1)]);
                Bm[j][p] = pack_pair(pb[(2 * p) * (NMO + 1)],
                                     pb[(2 * p + 1) * (NMO + 1)]);
            }
        }

        float det = 1.0f;

        #pragma unroll
        for (int k = 0; k < 8; k++) {
            const float piv = (k & 1) ? hi2(A[k][k >> 1]) : lo2(A[k][k >> 1]);
            const float nr  = -frcp(piv);
            minpiv = fminf(minpiv, fabsf(piv));
            det   *= piv;

            #pragma unroll
            for (int j = 0; j < 8; j++) {
                if (j == k) continue;
                const float akj = (k & 1) ? hi2(A[j][k >> 1]) : lo2(A[j][k >> 1]);
                const ull   nm  = pack2(akj * nr);   // (-m_j, -m_j)
                if (k < 7) {                          // A irrelevant after step 7
                    #pragma unroll
                    for (int p = 0; p < 4; p++)
                        if (p >= (k >> 1))            // rows < k of A col k ~ 0
                            A[j][p] = ffma2(nm, A[k][p], A[j][p]);
                }
                if (j < k) {
                    // Retired column: only its diagonal pair is still live.
                    Bm[j][j >> 1] = ffma2(nm, Bm[k][j >> 1], Bm[j][j >> 1]);
                } else {
                    #pragma unroll
                    for (int p = 0; p < 4; p++)
                        Bm[j][p] = ffma2(nm, Bm[k][p], Bm[j][p]);
                }
            }
        }

        // Trace: A is (numerically) diagonal with A[k][k] = pivot_k.
        float tr = 0.0f;
        #pragma unroll
        for (int k = 0; k < 8; k++) {
            const float dk = (k & 1) ? hi2(A[k][k >> 1])  : lo2(A[k][k >> 1]);
            const float bk = (k & 1) ? hi2(Bm[k][k >> 1]) : lo2(Bm[k][k >> 1]);
            tr = fmaf(bk, frcp(dk), tr);
        }

        trsum   += tr;
        detprod *= det;
    }

    if (minpiv >= PIV_THRESH) {
        out[(b0 + bl) * NCONF + c] = -0.5f * trsum * detprod;
    } else {
        const int s = atomicAdd(&sNbad, 1);   // shared-mem atomic, rare
        sBad[s] = tid;                        // tid encodes (bl, c)
    }
    __syncthreads();

    // ---------------- block-scope cleanup (rare) ----------------
    const int nbad = sNbad;
    if (nbad == 0) return;

    const int ll   = tid & 3;        // lane within 4-lane group
    const int lane = tid & 31;
    const int base = lane & 28;
    const int row0 = 2 * ll;
    const int row1 = 2 * ll + 1;

    for (int p0 = 0; p0 * 32 < nbad; p0++) {
        const int  e      = p0 * 32 + (tid >> 2);
        const bool active = (e < nbad);
        const int  gt  = sBad[active ? e : (nbad - 1)];   // clamp: full-mask shfl
        const int  gbl = gt >> 6;
        const int  gc  = gt & 63;

        float trs = 0.0f, detp = 1.0f;

        #pragma unroll 1
        for (int spin = 0; spin < 2; spin++) {
            const int4* cp = (const int4*)((spin ? cfg_dn : cfg_up) + gc * NSP);
            const int4  cAi = cp[0];
            const int4  cBi = cp[1];
            const int   cfg[8] = { cAi.x, cAi.y, cAi.z, cAi.w,
                                   cBi.x, cBi.y, cBi.z, cBi.w };
            const int   roff = spin ? NSP : 0;

            float c0[8], c1[8], e0[8], e1[8];
            #pragma unroll
            for (int j = 0; j < 8; j++) {
                const int col = cfg[j];
                c0[j] = sMO[gbl][roff + row0][col];
                c1[j] = sMO[gbl][roff + row1][col];
                e0[j] = sD2[gbl][roff + row0][col];
                e1[j] = sD2[gbl][roff + row1][col];
            }

            unsigned done0 = 0u, done1 = 0u;
            int   k0 = 0, k1 = 0;
            float p0v = 1.0f, p1v = 1.0f;
            int   dmask = 0, invtot = 0;

            #pragma unroll
            for (int k = 0; k < 8; k++) {
                unsigned key0 = done0 ? 0u
                    : ((__float_as_uint(fabsf(c0[k])) & 0xFFFFFFF8u) | (unsigned)row0);
                unsigned key1 = done1 ? 0u
                    : ((__float_as_uint(fabsf(c1[k])) & 0xFFFFFFF8u) | (unsigned)row1);
                unsigned key = max(key0, key1);
                key = max(key, __shfl_xor_sync(0xffffffffu, key, 1));
                key = max(key, __shfl_xor_sync(0xffffffffu, key, 2));

                const int  pr   = (int)(key & 7u);
                const int  pa   = base + (pr >> 1);
                const bool ps   = pr & 1;
                const bool isP0 = (row0 == pr);
                const bool isP1 = (row1 == pr);

                float pj[8];
                #pragma unroll
                for (int j = 0; j < 8; j++) {
                    if (j >= k) {
                        const float s = ps ? c1[j] : c0[j];
                        pj[j] = __shfl_sync(0xffffffffu, s, pa);
                    }
                }
                const float r  = frcp(pj[k]);
                const float m0 = isP0 ? 0.0f : c0[k] * r;
                const float m1 = isP1 ? 0.0f : c1[k] * r;

                if (isP0) { p0v = c0[k]; k0 = k; done0 = 1u; }
                if (isP1) { p1v = c1[k]; k1 = k; done1 = 1u; }

                #pragma unroll
                for (int j = 0; j < 8; j++) {
                    if (j > k) {
                        c0[j] = fmaf(-m0, pj[j], c0[j]);
                        c1[j] = fmaf(-m1, pj[j], c1[j]);
                    }
                }
                #pragma unroll
                for (int j = 0; j < 8; j++) {
                    const float s = ps ? e1[j] : e0[j];
                    const float q = __shfl_sync(0xffffffffu, s, pa);
                    e0[j] = fmaf(-m0, q, e0[j]);
                    e1[j] = fmaf(-m1, q, e1[j]);
                }

                invtot += __popc((unsigned)dmask >> (pr + 1));
                dmask  |= 1 << pr;
            }

            float bv0 = e0[0];
            #pragma unroll
            for (int j = 1; j < 8; j++) bv0 = (k0 == j) ? e0[j] : bv0;
            float bv1 = e1[0];
            #pragma unroll
            for (int j = 1; j < 8; j++) bv1 = (k1 == j) ? e1[j] : bv1;

            const float dd = p0v * p1v;
            float tr  = (bv0 * p1v + bv1 * p0v) * frcp(dd);
            float det = (ll == 0 && (invtot & 1)) ? -dd : dd;

            #pragma unroll
            for (int off = 1; off < 4; off <<= 1) {
                tr  += __shfl_xor_sync(0xffffffffu, tr,  off);
                det *= __shfl_xor_sync(0xffffffffu, det, off);
            }

            trs  += tr;
            detp *= det;
        }

        if (active && ll == 0)
            out[(b0 + gbl) * NCONF + gc] = -0.5f * trs * detp;
    }
}

extern "C" void kernel_launch(void* const* d_in, const int* in_sizes, int n_in,
                              void* d_out, int out_size)
{
    const float* MO     = (const float*)d_in[0];
    const float* d2MO   = (const float*)d_in[1];
    const int*   cfg_up = (const int*)d_in[2];
    const int*   cfg_dn = (const int*)d_in[3];
    float*       out    = (float*)d_out;

    kinetic_kernel<<<NBATCH / BPB, THREADS>>>(MO, d2MO, cfg_up, cfg_dn, out);
}

// round 16
// speedup vs baseline: 1.1048x; 1.0544x over previous
#include <cuda_runtime.h>

typedef unsigned long long ull;

// Problem constants (fixed by the dataset)
#define NBATCH 8192
#define NEL    16      // NUP + NDOWN
#define NSP    8
#define NMO    32
#define NCONF  64

#define PIV_THRESH 2.5e-4f   // N(0,1) inputs; below this, redo with pivoting

#define BPB     2                 // batches per block
#define THREADS (BPB * NCONF)     // 128

__device__ __forceinline__ float frcp(float x) {
    float r;
    asm("rcp.approx.f32 %0, %1;" : "=f"(r) : "f"(x));
    return r;
}

// f32x2 helpers: 64-bit carrier holds (lo=row 2p, hi=row 2p+1).
__device__ __forceinline__ ull pack2(float x) {
    ull r;
    asm("mov.b64 %0, {%1, %1};" : "=l"(r) : "r"(__float_as_uint(x)));
    return r;
}
__device__ __forceinline__ ull pack_pair(float lo, float hi) {
    ull r;
    asm("mov.b64 %0, {%1, %2};" : "=l"(r) : "f"(lo), "f"(hi));
    return r;
}
__device__ __forceinline__ float lo2(ull v) {
    return __uint_as_float((unsigned)v);
}
__device__ __forceinline__ float hi2(ull v) {
    return __uint_as_float((unsigned)(v >> 32));
}
__device__ __forceinline__ ull ffma2(ull a, ull b, ull c) {   // a*b + c, packed
    ull d;
    asm("fma.rn.f32x2 %0, %1, %2, %3;" : "=l"(d) : "l"(a), "l"(b), "l"(c));
    return d;
}

// ---------------------------------------------------------------------------
// ONE THREAD = ONE (batch, config) pair; block = 2 batches x 64 configs.
// Hot path: column-op Gauss-Jordan without pivoting (column ops preserve
// tr(A^-1 B); det = product of pivots), rows packed as f32x2. Round-13
// dead-pair skip on A (source column a[k] has ~0 in rows < k).
//
// This round: __launch_bounds__(THREADS, 4) caps registers at 128 to fit a
// 4th CTA per SM (12 -> 16 warps). The hot A/Bm arrays are statically
// indexed and stay in registers; the ~15 shed registers are cold scalars
// outside the k-loop. (If ptxas instead spills inside the loop, the L1%
// signature will show it and this experiment reverts.)
//
// SMEM layout [row][NMO+1]: warp-wide column gathers hit bank
// (row + col) mod 32 -> conflict-free (duplicates broadcast).
//
// Cleanup (block scope, rare): groups with |pivot| < PIV_THRESH are parked in
// a shared list and re-solved by the block's warps with the proven
// 4-lane/2-row ROW-op Gauss-Jordan + implicit partial pivoting.
// ---------------------------------------------------------------------------
__global__ __launch_bounds__(THREADS, 4)
void kinetic_kernel(const float* __restrict__ MO,
                    const float* __restrict__ d2MO,
                    const int*   __restrict__ cfg_up,
                    const int*   __restrict__ cfg_dn,
                    float*       __restrict__ out)
{
    __shared__ float sMO[BPB][NEL][NMO + 1];   // +1 pad: (row+col) bank spread
    __shared__ float sD2[BPB][NEL][NMO + 1];
    __shared__ int   sBad[THREADS];
    __shared__ int   sNbad;

    const int tid = threadIdx.x;
    const int b0  = blockIdx.x * BPB;

    if (tid == 0) sNbad = 0;

    // Stage: coalesced global reads; smem writes bank-conflict-free.
    #pragma unroll
    for (int i = 0; i < (BPB * NEL * NMO) / THREADS; i++) {
        const int e   = tid + i * THREADS;
        const int bl  = e >> 9;          // /512
        const int rem = e & 511;
        const int row = rem >> 5;        // electron 0..15
        const int col = rem & 31;        // MO 0..31
        sMO[bl][row][col] = MO[(b0 + bl) * NEL * NMO + rem];
        sD2[bl][row][col] = d2MO[(b0 + bl) * NEL * NMO + rem];
    }
    __syncthreads();

    const int bl = tid >> 6;   // batch within block
    const int c  = tid & 63;   // config

    float trsum   = 0.0f;
    float detprod = 1.0f;
    float minpiv  = 1e30f;

    #pragma unroll 1
    for (int spin = 0; spin < 2; spin++) {
        const int4* cp = (const int4*)((spin ? cfg_dn : cfg_up) + c * NSP);
        const int4  cA = cp[0];
        const int4  cB = cp[1];
        const int   cfg[8] = { cA.x, cA.y, cA.z, cA.w, cB.x, cB.y, cB.z, cB.w };
        const int   roff = spin ? NSP : 0;

        // A, B: 8 columns x 4 packed row-pairs. Conflict-free scalar gathers
        // (stride 33 within a column), packed to f32x2 in registers.
        ull A[8][4], Bm[8][4];
        #pragma unroll
        for (int j = 0; j < 8; j++) {
            const float* pa = &sMO[bl][roff][cfg[j]];
            const float* pb = &sD2[bl][roff][cfg[j]];
            #pragma unroll
            for (int p = 0; p < 4; p++) {
                A[j][p]  = pack_pair(pa[(2 * p) * (NMO + 1)],
                                     pa[(2 * p + 1) * (NMO + 1)]);
                Bm[j][p] = pack_pair(pb[(2 * p) * (NMO + 1)],
                                     pb[(2 * p + 1) * (NMO + 1)]);
            }
        }

        float det = 1.0f;

        #pragma unroll
        for (int k = 0; k < 8; k++) {
            const float piv = (k & 1) ? hi2(A[k][k >> 1]) : lo2(A[k][k >> 1]);
            const float nr  = -frcp(piv);
            minpiv = fminf(minpiv, fabsf(piv));
            det   *= piv;

            #pragma unroll
            for (int j = 0; j < 8; j++) {
                if (j == k) continue;
                const float akj = (k & 1) ? hi2(A[j][k >> 1]) : lo2(A[j][k >> 1]);
                const ull   nm  = pack2(akj * nr);   // (-m_j, -m_j)
                if (k < 7) {                          // A irrelevant after step 7
                    #pragma unroll
                    for (int p = 0; p < 4; p++)
                        if (p >= (k >> 1))            // rows < k of A col k ~ 0
                            A[j][p] = ffma2(nm, A[k][p], A[j][p]);
                }
                #pragma unroll
                for (int p = 0; p < 4; p++)
                    Bm[j][p] = ffma2(nm, Bm[k][p], Bm[j][p]);
            }
        }

        // Trace: A is (numerically) diagonal with A[k][k] = pivot_k.
        float tr = 0.0f;
        #pragma unroll
        for (int k = 0; k < 8; k++) {
            const float dk = (k & 1) ? hi2(A[k][k >> 1])  : lo2(A[k][k >> 1]);
            const float bk = (k & 1) ? hi2(Bm[k][k >> 1]) : lo2(Bm[k][k >> 1]);
            tr = fmaf(bk, frcp(dk), tr);
        }

        trsum   += tr;
        detprod *= det;
    }

    if (minpiv >= PIV_THRESH) {
        out[(b0 + bl) * NCONF + c] = -0.5f * trsum * detprod;
    } else {
        const int s = atomicAdd(&sNbad, 1);   // shared-mem atomic, rare
        sBad[s] = tid;                        // tid encodes (bl, c)
    }
    __syncthreads();

    // ---------------- block-scope cleanup (rare) ----------------
    const int nbad = sNbad;
    if (nbad == 0) return;

    const int ll   = tid & 3;        // lane within 4-lane group
    const int lane = tid & 31;
    const int base = lane & 28;
    const int row0 = 2 * ll;
    const int row1 = 2 * ll + 1;

    for (int p0 = 0; p0 * 32 < nbad; p0++) {
        const int  e      = p0 * 32 + (tid >> 2);
        const bool active = (e < nbad);
        const int  gt  = sBad[active ? e : (nbad - 1)];   // clamp: full-mask shfl
        const int  gbl = gt >> 6;
        const int  gc  = gt & 63;

        float trs = 0.0f, detp = 1.0f;

        #pragma unroll 1
        for (int spin = 0; spin < 2; spin++) {
            const int4* cp = (const int4*)((spin ? cfg_dn : cfg_up) + gc * NSP);
            const int4  cAi = cp[0];
            const int4  cBi = cp[1];
            const int   cfg[8] = { cAi.x, cAi.y, cAi.z, cAi.w,
                                   cBi.x, cBi.y, cBi.z, cBi.w };
            const int   roff = spin ? NSP : 0;

            float c0[8], c1[8], e0[8], e1[8];
            #pragma unroll
            for (int j = 0; j < 8; j++) {
                const int col = cfg[j];
                c0[j] = sMO[gbl][roff + row0][col];
                c1[j] = sMO[gbl][roff + row1][col];
                e0[j] = sD2[gbl][roff + row0][col];
                e1[j] = sD2[gbl][roff + row1][col];
            }

            unsigned done0 = 0u, done1 = 0u;
            int   k0 = 0, k1 = 0;
            float p0v = 1.0f, p1v = 1.0f;
            int   dmask = 0, invtot = 0;

            #pragma unroll
            for (int k = 0; k < 8; k++) {
                unsigned key0 = done0 ? 0u
                    : ((__float_as_uint(fabsf(c0[k])) & 0xFFFFFFF8u) | (unsigned)row0);
                unsigned key1 = done1 ? 0u
                    : ((__float_as_uint(fabsf(c1[k])) & 0xFFFFFFF8u) | (unsigned)row1);
                unsigned key = max(key0, key1);
                key = max(key, __shfl_xor_sync(0xffffffffu, key, 1));
                key = max(key, __shfl_xor_sync(0xffffffffu, key, 2));

                const int  pr   = (int)(key & 7u);
                const int  pa   = base + (pr >> 1);
                const bool ps   = pr & 1;
                const bool isP0 = (row0 == pr);
                const bool isP1 = (row1 == pr);

                float pj[8];
                #pragma unroll
                for (int j = 0; j < 8; j++) {
                    if (j >= k) {
                        const float s = ps ? c1[j] : c0[j];
                        pj[j] = __shfl_sync(0xffffffffu, s, pa);
                    }
                }
                const float r  = frcp(pj[k]);
                const float m0 = isP0 ? 0.0f : c0[k] * r;
                const float m1 = isP1 ? 0.0f : c1[k] * r;

                if (isP0) { p0v = c0[k]; k0 = k; done0 = 1u; }
                if (isP1) { p1v = c1[k]; k1 = k; done1 = 1u; }

                #pragma unroll
                for (int j = 0; j < 8; j++) {
                    if (j > k) {
                        c0[j] = fmaf(-m0, pj[j], c0[j]);
                        c1[j] = fmaf(-m1, pj[j], c1[j]);
                    }
                }
                #pragma unroll
                for (int j = 0; j < 8; j++) {
                    const float s = ps ? e1[j] : e0[j];
                    const float q = __shfl_sync(0xffffffffu, s, pa);
                    e0[j] = fmaf(-m0, q, e0[j]);
                    e1[j] = fmaf(-m1, q, e1[j]);
                }

                invtot += __popc((unsigned)dmask >> (pr + 1));
                dmask  |= 1 << pr;
            }

            float bv0 = e0[0];
            #pragma unroll
            for (int j = 1; j < 8; j++) bv0 = (k0 == j) ? e0[j] : bv0;
            float bv1 = e1[0];
            #pragma unroll
            for (int j = 1; j < 8; j++) bv1 = (k1 == j) ? e1[j] : bv1;

            const float dd = p0v * p1v;
            float tr  = (bv0 * p1v + bv1 * p0v) * frcp(dd);
            float det = (ll == 0 && (invtot & 1)) ? -dd : dd;

            #pragma unroll
            for (int off = 1; off < 4; off <<= 1) {
                tr  += __shfl_xor_sync(0xffffffffu, tr,  off);
                det *= __shfl_xor_sync(0xffffffffu, det, off);
            }

            trs  += tr;
            detp *= det;
        }

        if (active && ll == 0)
            out[(b0 + gbl) * NCONF + gc] = -0.5f * trs * detp;
    }
}

extern "C" void kernel_launch(void* const* d_in, const int* in_sizes, int n_in,
                              void* d_out, int out_size)
{
    const float* MO     = (const float*)d_in[0];
    const float* d2MO   = (const float*)d_in[1];
    const int*   cfg_up = (const int*)d_in[2];
    const int*   cfg_dn = (const int*)d_in[3];
    float*       out    = (float*)d_out;

    kinetic_kernel<<<NBATCH / BPB, THREADS>>>(MO, d2MO, cfg_up, cfg_dn, out);
}